// round 7
// baseline (speedup 1.0000x reference)
#include <cuda_runtime.h>
#include <cstdint>

// Problem constants
#define RES    64
#define C_CH   8
#define NB     64
#define CORE   32
#define POS    16                        // (RES-CORE)/2
#define DIM    (CORE*CORE*CORE*C_CH)     // 262144
#define BATCH  32
#define VOL    (RES*RES*RES)             // 262144
#define BSTRIDE (C_CH*VOL)               // 2097152 floats per batch

#define TPB 256
#define BPH 16                           // batches per compute block (half of 32)
#define NCOMPUTE (2 * DIM / TPB)         // 2048 compute blocks
#define SLABS_PER_ZBLOCK 16
#define NZERO  (BATCH * C_CH * RES / SLABS_PER_ZBLOCK)   // 1024 fat zero blocks
// grid = 3072 groups-of-3: rem 0,1 -> compute, rem 2 -> zero

// ---- packed fp32x2 helpers (sm_10x FFMA2) ----
__device__ __forceinline__ unsigned long long pack2(float lo, float hi) {
    unsigned long long r;
    asm("mov.b64 %0, {%1, %2};" : "=l"(r) : "f"(lo), "f"(hi));
    return r;
}
__device__ __forceinline__ void unpack2(unsigned long long v, float& lo, float& hi) {
    asm("mov.b64 {%0, %1}, %2;" : "=f"(lo), "=f"(hi) : "l"(v));
}
__device__ __forceinline__ unsigned long long fma2(unsigned long long a,
                                                   unsigned long long b,
                                                   unsigned long long c) {
    unsigned long long r;
    asm("fma.rn.f32x2 %0, %1, %2, %3;" : "=l"(r) : "l"(a), "l"(b), "l"(c));
    return r;
}

// Fused kernel, 3072 blocks in groups of 3:
//   rem 0,1 : GEMM core fill (cidx = 2*grp + rem; pair shares U stripe)
//   rem 2   : zero periphery of 16 consecutive (b,c,i) slabs (fat block —
//             avoids the CTA-churn of 16384 tiny blocks)
__global__ __launch_bounds__(TPB)
void core_part_fused(const float* __restrict__ z,
                     const float* __restrict__ U,
                     const float* __restrict__ L,
                     const float* __restrict__ mu,
                     float* __restrict__ out) {
    const unsigned tid = threadIdx.x;
    const unsigned bid = blockIdx.x;
    const unsigned grp = bid / 3;
    const unsigned rem = bid - grp * 3;

    if (rem == 2) {
        // ------------- zero periphery of 16 consecutive slabs -------------
        const unsigned zidx = grp;                        // 0..1023
        const float4 zz = make_float4(0.f, 0.f, 0.f, 0.f);

        #pragma unroll
        for (unsigned s = 0; s < SLABS_PER_ZBLOCK; s++) {
            const unsigned slab = zidx * SLABS_PER_ZBLOCK + s;   // 0..16383
            const unsigned i = slab & 63;
            const unsigned c = (slab >> 6) & 7;
            const unsigned b = slab >> 9;
            float4* base = reinterpret_cast<float4*>(
                out + (unsigned)(b * BSTRIDE + c * VOL + i * (RES * RES)));

            if (i < POS || i >= POS + CORE) {
                // whole 64x64 slab is periphery: 1024 float4
                #pragma unroll
                for (unsigned idx = tid; idx < 1024; idx += TPB)
                    __stcs(&base[idx], zz);
            } else {
                // core-i slab: 32 full periphery rows (512 f4) + k-edges (256 f4)
                #pragma unroll
                for (unsigned idx = tid; idx < 768; idx += TPB) {
                    if (idx < 512) {
                        unsigned row = idx >> 4;                 // 0..31
                        unsigned jj = (row < POS) ? row : row + CORE;
                        unsigned col4 = idx & 15;
                        __stcs(&base[jj * 16 + col4], zz);
                    } else {
                        unsigned t = idx - 512;                  // 0..255
                        unsigned row = t >> 3;                   // 0..31
                        unsigned j = row + POS;
                        unsigned q = t & 7;
                        unsigned k4 = (q < 4) ? q : q + 8;       // f4 idx in row
                        __stcs(&base[j * 16 + k4], zz);
                    }
                }
            }
        }
        return;
    }

    // ---------------- GEMM core fill (16 batches per block) ----------------
    const unsigned cidx   = grp * 2 + rem;                // 0..2047
    const unsigned stripe = cidx >> 1;                    // 0..1023 : d-stripe
    const unsigned bhalf  = (cidx & 1) * BPH;             // 0 or 16 : batch offset

    __shared__ __align__(16) float a_s[NB * BPH];         // a_s[n*16+bl]=L[n]*z[bhalf+bl,n]

    #pragma unroll
    for (unsigned idx = tid; idx < NB * BPH; idx += TPB) {
        unsigned n  = idx >> 4;                           // 0..63
        unsigned bl = idx & 15;                           // 0..15
        a_s[idx] = L[n] * z[(bhalf + bl) * NB + n];
    }
    __syncthreads();

    const unsigned d = stripe * TPB + tid;                // contiguous per warp

    unsigned long long acc[BPH / 2];                      // f32x2: batches (2p,2p+1)
    #pragma unroll
    for (int p = 0; p < BPH / 2; p++) acc[p] = 0ull;

    const ulonglong2* a_v = reinterpret_cast<const ulonglong2*>(a_s); // 4 per n

    #pragma unroll 8
    for (unsigned n = 0; n < NB; n++) {
        float u = __ldg(&U[n * (unsigned)DIM + d]);
        unsigned long long u2 = pack2(u, u);
        #pragma unroll
        for (int q = 0; q < 4; q++) {                     // 4 * ulonglong2 = 16 batches
            ulonglong2 av = a_v[n * 4 + q];
            acc[q * 2 + 0] = fma2(av.x, u2, acc[q * 2 + 0]);
            acc[q * 2 + 1] = fma2(av.y, u2, acc[q * 2 + 1]);
        }
    }

    const float m = mu[d];

    const unsigned k = d & 31;
    const unsigned j = (d >> 5) & 31;
    const unsigned i = (d >> 10) & 31;
    const unsigned c = d >> 15;

    const unsigned base = c * VOL
                        + (i + POS) * (RES * RES)
                        + (j + POS) * RES
                        + (k + POS)
                        + bhalf * (unsigned)BSTRIDE;

    #pragma unroll
    for (int p = 0; p < BPH / 2; p++) {
        float lo, hi;
        unpack2(acc[p], lo, hi);
        __stcs(&out[base + (unsigned)(2 * p + 0) * BSTRIDE], lo + m);
        __stcs(&out[base + (unsigned)(2 * p + 1) * BSTRIDE], hi + m);
    }
}

extern "C" void kernel_launch(void* const* d_in, const int* in_sizes, int n_in,
                              void* d_out, int out_size) {
    const float* z  = (const float*)d_in[0];   // (32, 64)
    const float* U  = (const float*)d_in[1];   // (64, 262144)
    const float* L  = (const float*)d_in[2];   // (64,)
    const float* mu = (const float*)d_in[3];   // (262144,)
    float* out = (float*)d_out;                // (32, 8, 64, 64, 64)

    core_part_fused<<<NCOMPUTE + NZERO, TPB>>>(z, U, L, mu, out);
}

// round 8
// speedup vs baseline: 1.0810x; 1.0810x over previous
#include <cuda_runtime.h>
#include <cstdint>

// Problem constants
#define RES    64
#define C_CH   8
#define NB     64
#define CORE   32
#define POS    16                        // (RES-CORE)/2
#define DIM    (CORE*CORE*CORE*C_CH)     // 262144
#define BATCH  32
#define VOL    (RES*RES*RES)             // 262144
#define BSTRIDE (C_CH*VOL)               // 2097152 floats per batch

#define TPB 256
#define BPB 8                            // batches per compute block
#define DPT 4                            // d-values per thread (one LDG.128 of U)
// compute block covers 1024 d (256 thr * 4) x 8 batches
#define NCOMPUTE ((DIM / (TPB * DPT)) * (BATCH / BPB))   // 256 * 4 = 1024
#define NSLABS   (BATCH * C_CH * RES)                    // 16384 zero-slab blocks

// ---- packed fp32x2 helpers (sm_10x FFMA2) ----
__device__ __forceinline__ unsigned long long pack2(float lo, float hi) {
    unsigned long long r;
    asm("mov.b64 %0, {%1, %2};" : "=l"(r) : "f"(lo), "f"(hi));
    return r;
}
__device__ __forceinline__ unsigned long long fma2(unsigned long long a,
                                                   unsigned long long b,
                                                   unsigned long long c) {
    unsigned long long r;
    asm("fma.rn.f32x2 %0, %1, %2, %3;" : "=l"(r) : "l"(a), "l"(b), "l"(c));
    return r;
}
__device__ __forceinline__ unsigned long long add2(unsigned long long a,
                                                   unsigned long long b) {
    unsigned long long r;
    asm("add.rn.f32x2 %0, %1, %2;" : "=l"(r) : "l"(a), "l"(b));
    return r;
}

// Fused kernel:
//   blocks [0, NCOMPUTE)       : GEMM core fill; groups of 4 adjacent blocks share
//                                one U d-stripe (L2 reuse), each covering 8 batches.
//                                Thread = 4 consecutive d (LDG.128 U, STG.128 out).
//   blocks [NCOMPUTE, +NSLABS) : zero the periphery of one (b,c,i) 64x64 slab
__global__ __launch_bounds__(TPB)
void core_part_fused(const float* __restrict__ z,
                     const float* __restrict__ U,
                     const float* __restrict__ L,
                     const float* __restrict__ mu,
                     float* __restrict__ out) {
    const unsigned tid = threadIdx.x;

    if (blockIdx.x >= NCOMPUTE) {
        // ---------------- zero-fill one (b,c,i) slab's periphery ----------------
        const unsigned slab = blockIdx.x - NCOMPUTE;
        const unsigned i = slab & 63;
        const unsigned c = (slab >> 6) & 7;
        const unsigned b = slab >> 9;
        float4* base = reinterpret_cast<float4*>(
            out + (unsigned)(b * BSTRIDE + c * VOL + i * (RES * RES)));
        const float4 zz = make_float4(0.f, 0.f, 0.f, 0.f);

        if (i < POS || i >= POS + CORE) {
            // whole 64x64 slab is periphery: 1024 float4
            #pragma unroll
            for (unsigned idx = tid; idx < 1024; idx += TPB)
                base[idx] = zz;
        } else {
            // core-i slab: 32 full periphery rows (512 f4) + k-edges (256 f4)
            #pragma unroll
            for (unsigned idx = tid; idx < 768; idx += TPB) {
                if (idx < 512) {
                    unsigned row = idx >> 4;                 // 0..31
                    unsigned jj = (row < POS) ? row : row + CORE;
                    unsigned col4 = idx & 15;
                    base[jj * 16 + col4] = zz;
                } else {
                    unsigned t = idx - 512;                  // 0..255
                    unsigned row = t >> 3;                   // 0..31
                    unsigned j = row + POS;
                    unsigned q = t & 7;
                    unsigned k4 = (q < 4) ? q : q + 8;       // f4 idx in row
                    base[j * 16 + k4] = zz;
                }
            }
        }
        return;
    }

    // ---------------- GEMM core fill (4 d x 8 batches per thread) ----------------
    const unsigned cidx   = blockIdx.x;
    const unsigned stripe = cidx >> 2;                     // 0..255 : 1024-d stripe
    const unsigned bg     = (cidx & 3) * BPB;              // batch group: 0/8/16/24

    // Pre-duplicated coefficients: a2[n*8 + bl] = {a, a}, a = L[n]*z[bg+bl, n]
    __shared__ __align__(16) float2 a_s[NB * BPB];         // 4 KB

    #pragma unroll
    for (unsigned idx = tid; idx < NB * BPB; idx += TPB) {
        unsigned n  = idx >> 3;                            // 0..63
        unsigned bl = idx & 7;                             // 0..7
        float a = L[n] * z[(bg + bl) * NB + n];
        a_s[idx] = make_float2(a, a);
    }
    __syncthreads();

    const unsigned du = stripe * TPB + tid;                // float4-index into U row

    unsigned long long acc0[BPB], acc1[BPB];               // per batch: d0d1, d2d3
    #pragma unroll
    for (int b = 0; b < BPB; b++) { acc0[b] = 0ull; acc1[b] = 0ull; }

    const float4* U4 = reinterpret_cast<const float4*>(U);
    const ulonglong2* a_v = reinterpret_cast<const ulonglong2*>(a_s); // 4 per n

    #pragma unroll 8
    for (unsigned n = 0; n < NB; n++) {
        float4 uv = __ldg(&U4[n * (unsigned)(DIM / 4) + du]);
        unsigned long long u01 = pack2(uv.x, uv.y);
        unsigned long long u23 = pack2(uv.z, uv.w);
        #pragma unroll
        for (int q = 0; q < 4; q++) {                      // 2 batches per iter
            ulonglong2 av = a_v[n * 4 + q];                // broadcast LDS.128
            acc0[2*q+0] = fma2(u01, av.x, acc0[2*q+0]);
            acc1[2*q+0] = fma2(u23, av.x, acc1[2*q+0]);
            acc0[2*q+1] = fma2(u01, av.y, acc0[2*q+1]);
            acc1[2*q+1] = fma2(u23, av.y, acc1[2*q+1]);
        }
    }

    const float4 mv = __ldg(&reinterpret_cast<const float4*>(mu)[du]);
    const unsigned long long m01 = pack2(mv.x, mv.y);
    const unsigned long long m23 = pack2(mv.z, mv.w);

    // Decompose first d of this thread -> (c, i, j, k); k is a multiple of 4
    const unsigned d0 = du * DPT;
    const unsigned k = d0 & 31;
    const unsigned j = (d0 >> 5) & 31;
    const unsigned i = (d0 >> 10) & 31;
    const unsigned c = d0 >> 15;

    const unsigned base = c * VOL
                        + (i + POS) * (RES * RES)
                        + (j + POS) * RES
                        + (k + POS)
                        + bg * (unsigned)BSTRIDE;

    #pragma unroll
    for (int b = 0; b < BPB; b++) {
        unsigned long long r0 = add2(acc0[b], m01);
        unsigned long long r1 = add2(acc1[b], m23);
        // 16B-aligned (k+POS multiple of 4), fully coalesced across the warp
        *reinterpret_cast<ulonglong2*>(&out[base + (unsigned)b * BSTRIDE]) =
            make_ulonglong2(r0, r1);
    }
}

extern "C" void kernel_launch(void* const* d_in, const int* in_sizes, int n_in,
                              void* d_out, int out_size) {
    const float* z  = (const float*)d_in[0];   // (32, 64)
    const float* U  = (const float*)d_in[1];   // (64, 262144)
    const float* L  = (const float*)d_in[2];   // (64,)
    const float* mu = (const float*)d_in[3];   // (262144,)
    float* out = (float*)d_out;                // (32, 8, 64, 64, 64)

    core_part_fused<<<NCOMPUTE + NSLABS, TPB>>>(z, U, L, mu, out);
}